// round 14
// baseline (speedup 1.0000x reference)
#include <cuda_runtime.h>
#include <cstdint>

// FANSNeuralOutputUpdate on GB300 (sm_103a), round 12.
// R11 kernel (group-packed f32x2, z-dup, NB=2, 10-ull weight records,
// pointer-incremented) with ONE change: __launch_bounds__(256, 6).
// ptxas chose 46 regs under the 5-CTA cap; 42 regs fits 6 CTAs/SM
// -> 48 warps/SM (+20% occupancy), same instruction count if no loop spills.

#define B_TILE     64    // batches per block (= 32 lanes * NB)
#define GP_BLOCK   8     // group-pairs per block (warp w -> (gp0+w, gp0+w+32))
#define NB         2     // batch rows per lane
#define THREADS    256
#define WH_STRIDE  10    // ull per (g,h) record: wk[8], bb, w2k

typedef unsigned long long ull;

__device__ __forceinline__ ull pack2(float lo, float hi) {
    ull r; asm("mov.b64 %0, {%1, %2};" : "=l"(r) : "f"(lo), "f"(hi)); return r;
}
__device__ __forceinline__ void unpack2(ull v, float& lo, float& hi) {
    asm("mov.b64 {%0, %1}, %2;" : "=f"(lo), "=f"(hi) : "l"(v));
}
__device__ __forceinline__ ull ffma2(ull a, ull b, ull c) {
    ull d; asm("fma.rn.f32x2 %0, %1, %2, %3;" : "=l"(d) : "l"(a), "l"(b), "l"(c)); return d;
}
__device__ __forceinline__ float tanh_hw(float x) {
    float r; asm("tanh.approx.f32 %0, %1;" : "=f"(r) : "f"(x)); return r;
}

__global__ __launch_bounds__(THREADS, 6)
void fans_kernel(const float* __restrict__ x_f,     // (B,16)
                 const float* __restrict__ x_b,     // (B,16)
                 const int*   __restrict__ sel_idx, // (64,8)
                 const float* __restrict__ W1,      // (64,8,32)
                 const float* __restrict__ b1,      // (64,32)
                 const float* __restrict__ W2,      // (64,32,1)
                 const float* __restrict__ b2,      // (64,1)
                 float*       __restrict__ out,     // (B,64)
                 int Btot)
{
    __shared__ float xs[B_TILE * 33];                     // row-major, stride 33
    __shared__ __align__(16) ull wh[GP_BLOCK][32][WH_STRIDE];
    __shared__ int   sels[GP_BLOCK][8];
    __shared__ ull   b2p[GP_BLOCK];
    __shared__ float ys[B_TILE * 17];

    const int tid    = threadIdx.x;
    const int batch0 = blockIdx.x * B_TILE;
    const int gp0    = blockIdx.y * GP_BLOCK;

    // ---- stage x tile (coalesced over j) ----
    for (int i = tid; i < B_TILE * 32; i += THREADS) {
        int bl = i >> 5, j = i & 31;
        int bg = batch0 + bl;
        float v = 0.0f;
        if (bg < Btot)
            v = (j < 16) ? x_f[bg * 16 + j] : x_b[bg * 16 + (j - 16)];
        xs[bl * 33 + j] = v;
    }

    // ---- stage weight records: exactly one thread per (gpl, h) ----
    {
        int gpl = tid >> 5, h = tid & 31;      // 256 threads == 8*32 records
        int gA = gp0 + gpl, gB = gA + 32;
        ull* rec = wh[gpl][h];
#pragma unroll
        for (int k = 0; k < 8; k++)
            rec[k] = pack2(W1[(gA * 8 + k) * 32 + h], W1[(gB * 8 + k) * 32 + h]);
        rec[8] = pack2(b1[gA * 32 + h], b1[gB * 32 + h]);   // chain seed {b1A,b1B}
        rec[9] = pack2(W2[gA * 32 + h], W2[gB * 32 + h]);
    }
    if (tid < GP_BLOCK * 8) {
        int gpl = tid >> 3, k = tid & 7;
        sels[gpl][k] = sel_idx[(gp0 + gpl) * 8 + k];   // sel[g] == sel[g+32]
    }
    if (tid < GP_BLOCK)
        b2p[tid] = pack2(b2[gp0 + tid], b2[gp0 + tid + 32]);
    __syncthreads();

    const int wid = tid >> 5, lane = tid & 31;

    int col[8];
#pragma unroll
    for (int k = 0; k < 8; k++) col[k] = sels[wid][k];

    // ---- z duplicated into both f32x2 halves (prologue; col regs die here) ----
    ull zd[NB][8];
#pragma unroll
    for (int j = 0; j < NB; j++) {
        const float* row = &xs[(lane + 32 * j) * 33];
#pragma unroll
        for (int k = 0; k < 8; k++) {
            float v = row[col[k]];
            zd[j][k] = pack2(v, v);
        }
    }

    ull y2[NB];
    {
        ull b2v = b2p[wid];
#pragma unroll
        for (int j = 0; j < NB; j++) y2[j] = b2v;
    }

    // ---- main loop over hidden units (unroll 1: keep live regs small) ----
    const ull* rec = wh[wid][0];
#pragma unroll 1
    for (int h = 0; h < 32; h++) {
        ulonglong2 w01 = *(const ulonglong2*)&rec[0];
        ulonglong2 w23 = *(const ulonglong2*)&rec[2];
        ulonglong2 w45 = *(const ulonglong2*)&rec[4];
        ulonglong2 w67 = *(const ulonglong2*)&rec[6];
        ulonglong2 bw  = *(const ulonglong2*)&rec[8];   // {bb={b1A,b1B}, w2k}
        rec += WH_STRIDE;
#pragma unroll
        for (int j = 0; j < NB; j++) {
            ull acc = ffma2(zd[j][0], w01.x, bw.x);     // seeded with {b1A,b1B}
            acc = ffma2(zd[j][1], w01.y, acc);
            acc = ffma2(zd[j][2], w23.x, acc);
            acc = ffma2(zd[j][3], w23.y, acc);
            acc = ffma2(zd[j][4], w45.x, acc);
            acc = ffma2(zd[j][5], w45.y, acc);
            acc = ffma2(zd[j][6], w67.x, acc);
            acc = ffma2(zd[j][7], w67.y, acc);
            float a, b;
            unpack2(acc, a, b);                         // {preactA, preactB}
            y2[j] = ffma2(pack2(tanh_hw(a), tanh_hw(b)), bw.y, y2[j]);
        }
    }

    // ---- stage results, then full-sector coalesced writes ----
#pragma unroll
    for (int j = 0; j < NB; j++) {
        int bl = lane + 32 * j;
        float a, b;
        unpack2(y2[j], a, b);
        ys[bl * 17 + wid]     = a;   // column gp0+wid
        ys[bl * 17 + 8 + wid] = b;   // column gp0+wid+32
    }
    __syncthreads();

    for (int e = tid; e < B_TILE * 16; e += THREADS) {
        int bl = e >> 4, c = e & 15;
        int bg = batch0 + bl;
        if (bg < Btot) {
            int colg = gp0 + ((c < 8) ? c : (c + 24));
            out[bg * 64 + colg] = ys[bl * 17 + c];
        }
    }
}

extern "C" void kernel_launch(void* const* d_in, const int* in_sizes, int n_in,
                              void* d_out, int out_size)
{
    const float* x_f = (const float*)d_in[0];
    const float* x_b = (const float*)d_in[1];
    const int*   sel = (const int*)  d_in[2];
    const float* W1  = (const float*)d_in[3];
    const float* b1  = (const float*)d_in[4];
    const float* W2  = (const float*)d_in[5];
    const float* b2  = (const float*)d_in[6];
    float*       out = (float*)d_out;

    int Btot = in_sizes[0] / 16;                                   // 65536
    dim3 grid((Btot + B_TILE - 1) / B_TILE, 64 / (2 * GP_BLOCK));  // (1024, 4)
    fans_kernel<<<grid, THREADS>>>(x_f, x_b, sel, W1, b1, W2, b2, out, Btot);
}

// round 16
// speedup vs baseline: 1.0830x; 1.0830x over previous
#include <cuda_runtime.h>
#include <cstdint>

// FANSNeuralOutputUpdate on GB300 (sm_103a), round 15.
// tcgen05 path is blocked (harness compiles via compute_103 virtual arch,
// no 'a' suffix -> tcgen05 PTX rejected). SIMT path, R11 base:
// group-packed f32x2 (z-dup {v,v}), NB=2, 10-ull weight records.
// Changes vs R11: h-loop unroll 2 + manual interleave of the two j chains
// (kill RAW bubbles, hide LDS latency across iterations),
// __launch_bounds__(256,4) to give the unroll register headroom.

#define B_TILE     64    // batches per block (= 32 lanes * NB)
#define GP_BLOCK   8     // group-pairs per block (warp w -> (gp0+w, gp0+w+32))
#define NB         2     // batch rows per lane
#define THREADS    256
#define WH_STRIDE  10    // ull per (g,h) record: wk[8], bb, w2k

typedef unsigned long long ull;

__device__ __forceinline__ ull pack2(float lo, float hi) {
    ull r; asm("mov.b64 %0, {%1, %2};" : "=l"(r) : "f"(lo), "f"(hi)); return r;
}
__device__ __forceinline__ void unpack2(ull v, float& lo, float& hi) {
    asm("mov.b64 {%0, %1}, %2;" : "=f"(lo), "=f"(hi) : "l"(v));
}
__device__ __forceinline__ ull ffma2(ull a, ull b, ull c) {
    ull d; asm("fma.rn.f32x2 %0, %1, %2, %3;" : "=l"(d) : "l"(a), "l"(b), "l"(c)); return d;
}
__device__ __forceinline__ float tanh_hw(float x) {
    float r; asm("tanh.approx.f32 %0, %1;" : "=f"(r) : "f"(x)); return r;
}

__global__ __launch_bounds__(THREADS, 4)
void fans_kernel(const float* __restrict__ x_f,     // (B,16)
                 const float* __restrict__ x_b,     // (B,16)
                 const int*   __restrict__ sel_idx, // (64,8)
                 const float* __restrict__ W1,      // (64,8,32)
                 const float* __restrict__ b1,      // (64,32)
                 const float* __restrict__ W2,      // (64,32,1)
                 const float* __restrict__ b2,      // (64,1)
                 float*       __restrict__ out,     // (B,64)
                 int Btot)
{
    __shared__ float xs[B_TILE * 33];                     // row-major, stride 33
    __shared__ __align__(16) ull wh[GP_BLOCK][32][WH_STRIDE];
    __shared__ int   sels[GP_BLOCK][8];
    __shared__ ull   b2p[GP_BLOCK];
    __shared__ float ys[B_TILE * 17];

    const int tid    = threadIdx.x;
    const int batch0 = blockIdx.x * B_TILE;
    const int gp0    = blockIdx.y * GP_BLOCK;

    // ---- stage x tile (coalesced over j) ----
    for (int i = tid; i < B_TILE * 32; i += THREADS) {
        int bl = i >> 5, j = i & 31;
        int bg = batch0 + bl;
        float v = 0.0f;
        if (bg < Btot)
            v = (j < 16) ? x_f[bg * 16 + j] : x_b[bg * 16 + (j - 16)];
        xs[bl * 33 + j] = v;
    }

    // ---- stage weight records: exactly one thread per (gpl, h) ----
    {
        int gpl = tid >> 5, h = tid & 31;      // 256 threads == 8*32 records
        int gA = gp0 + gpl, gB = gA + 32;
        ull* rec = wh[gpl][h];
#pragma unroll
        for (int k = 0; k < 8; k++)
            rec[k] = pack2(W1[(gA * 8 + k) * 32 + h], W1[(gB * 8 + k) * 32 + h]);
        rec[8] = pack2(b1[gA * 32 + h], b1[gB * 32 + h]);   // chain seed {b1A,b1B}
        rec[9] = pack2(W2[gA * 32 + h], W2[gB * 32 + h]);
    }
    if (tid < GP_BLOCK * 8) {
        int gpl = tid >> 3, k = tid & 7;
        sels[gpl][k] = sel_idx[(gp0 + gpl) * 8 + k];   // sel[g] == sel[g+32]
    }
    if (tid < GP_BLOCK)
        b2p[tid] = pack2(b2[gp0 + tid], b2[gp0 + tid + 32]);
    __syncthreads();

    const int wid = tid >> 5, lane = tid & 31;

    int col[8];
#pragma unroll
    for (int k = 0; k < 8; k++) col[k] = sels[wid][k];

    // ---- z duplicated into both f32x2 halves (prologue; col regs die here) ----
    ull zd[NB][8];
#pragma unroll
    for (int j = 0; j < NB; j++) {
        const float* row = &xs[(lane + 32 * j) * 33];
#pragma unroll
        for (int k = 0; k < 8; k++) {
            float v = row[col[k]];
            zd[j][k] = pack2(v, v);
        }
    }

    ull y0, y1;
    {
        ull b2v = b2p[wid];
        y0 = b2v; y1 = b2v;
    }

    // ---- main loop: unroll 2, two j chains interleaved ----
    const ull* rec = wh[wid][0];
#pragma unroll 2
    for (int h = 0; h < 32; h++) {
        ulonglong2 w01 = *(const ulonglong2*)&rec[0];
        ulonglong2 w23 = *(const ulonglong2*)&rec[2];
        ulonglong2 w45 = *(const ulonglong2*)&rec[4];
        ulonglong2 w67 = *(const ulonglong2*)&rec[6];
        ulonglong2 bw  = *(const ulonglong2*)&rec[8];   // {bb={b1A,b1B}, w2k}
        rec += WH_STRIDE;

        // interleaved dual chains: consecutive instrs are never dependent
        ull a0 = ffma2(zd[0][0], w01.x, bw.x);
        ull a1 = ffma2(zd[1][0], w01.x, bw.x);
        a0 = ffma2(zd[0][1], w01.y, a0);
        a1 = ffma2(zd[1][1], w01.y, a1);
        a0 = ffma2(zd[0][2], w23.x, a0);
        a1 = ffma2(zd[1][2], w23.x, a1);
        a0 = ffma2(zd[0][3], w23.y, a0);
        a1 = ffma2(zd[1][3], w23.y, a1);
        a0 = ffma2(zd[0][4], w45.x, a0);
        a1 = ffma2(zd[1][4], w45.x, a1);
        a0 = ffma2(zd[0][5], w45.y, a0);
        a1 = ffma2(zd[1][5], w45.y, a1);
        a0 = ffma2(zd[0][6], w67.x, a0);
        a1 = ffma2(zd[1][6], w67.x, a1);
        a0 = ffma2(zd[0][7], w67.y, a0);
        a1 = ffma2(zd[1][7], w67.y, a1);

        float a0lo, a0hi, a1lo, a1hi;
        unpack2(a0, a0lo, a0hi);
        unpack2(a1, a1lo, a1hi);
        float t0a = tanh_hw(a0lo);
        float t1a = tanh_hw(a1lo);
        float t0b = tanh_hw(a0hi);
        float t1b = tanh_hw(a1hi);
        y0 = ffma2(pack2(t0a, t0b), bw.y, y0);
        y1 = ffma2(pack2(t1a, t1b), bw.y, y1);
    }

    // ---- stage results, then full-sector coalesced writes ----
    {
        float a, b;
        unpack2(y0, a, b);
        ys[lane * 17 + wid]     = a;
        ys[lane * 17 + 8 + wid] = b;
        unpack2(y1, a, b);
        ys[(lane + 32) * 17 + wid]     = a;
        ys[(lane + 32) * 17 + 8 + wid] = b;
    }
    __syncthreads();

    for (int e = tid; e < B_TILE * 16; e += THREADS) {
        int bl = e >> 4, c = e & 15;
        int bg = batch0 + bl;
        if (bg < Btot) {
            int colg = gp0 + ((c < 8) ? c : (c + 24));
            out[bg * 64 + colg] = ys[bl * 17 + c];
        }
    }
}

extern "C" void kernel_launch(void* const* d_in, const int* in_sizes, int n_in,
                              void* d_out, int out_size)
{
    const float* x_f = (const float*)d_in[0];
    const float* x_b = (const float*)d_in[1];
    const int*   sel = (const int*)  d_in[2];
    const float* W1  = (const float*)d_in[3];
    const float* b1  = (const float*)d_in[4];
    const float* W2  = (const float*)d_in[5];
    const float* b2  = (const float*)d_in[6];
    float*       out = (float*)d_out;

    int Btot = in_sizes[0] / 16;                                   // 65536
    dim3 grid((Btot + B_TILE - 1) / B_TILE, 64 / (2 * GP_BLOCK));  // (1024, 4)
    fans_kernel<<<grid, THREADS>>>(x_f, x_b, sel, W1, b1, W2, b2, out, Btot);
}